// round 5
// baseline (speedup 1.0000x reference)
#include <cuda_runtime.h>

// Grouped 3-tap width conv with cyclic rolls, fp32.
// Split-K (S=8) with direct REDG atomics into out (zeroed by a memset node).
// No scratch, no fence, no grid barrier, no reduce kernel.
//
// y[o,k,n,m] = sum_{i,j} f[o,i,n,m+j] * w[i,k,j],  f[u] = r[u-1] zero-padded,
// r = width-rolled x; height roll baked into the atomic destination index.
//
// Block: (kb, s): 32 output channels as 16 pairs (k, k+16), 64 input channels.
// Warp = (row 0..13, ihalf 0..1); lane = (isub 0..1, kp 0..15): each lane does
// 16 input channels; merge isub via shfl.xor(16), ihalf via smem, then REDG.

#define S_SPLITS 8
#define CI       64              // 512 / S_SPLITS input channels per block
#define NKT      16              // k-tiles: TK=32 channels each (16 pairs)
#define ROWS     14              // 2 groups * 7 heights
#define WARPS    (ROWS * 2)      // 28
#define THREADS  (WARPS * 32)    // 896
#define SMEM_IN  (CI * ROWS * 10 * 8)        // 71680 B  (float2 dup pairs)
#define SMEM_WA  (CI * 16 * 16)              // 16384 B  (ulonglong2 w0,w1 pairs)
#define SMEM_WB  (CI * 16 * 8)               //  8192 B  (ull w2 pairs)
#define SMEM_TOT (SMEM_IN + SMEM_WA + SMEM_WB)   // 96256 B

typedef unsigned long long ull;

__device__ __forceinline__ ull ffma2(ull a, ull b, ull c)
{
    ull d;
    asm("fma.rn.f32x2 %0, %1, %2, %3;" : "=l"(d) : "l"(a), "l"(b), "l"(c));
    return d;
}
__device__ __forceinline__ ull fadd2(ull a, ull b)
{
    ull d;
    asm("add.rn.f32x2 %0, %1, %2;" : "=l"(d) : "l"(a), "l"(b));
    return d;
}

__global__ __launch_bounds__(THREADS) void conv_atomic(const float* __restrict__ x,
                                                       const float* __restrict__ w,
                                                       float* __restrict__ out)
{
    extern __shared__ char dynsmem[];
    float2*     sInd = reinterpret_cast<float2*>(dynsmem);               // [CI][ROWS][10]
    ulonglong2* sWa  = reinterpret_cast<ulonglong2*>(dynsmem + SMEM_IN); // [CI][16]
    ull*        sWb  = reinterpret_cast<ull*>(dynsmem + SMEM_IN + SMEM_WA); // [CI][16]

    const int tid   = threadIdx.x;
    const int kb    = blockIdx.x;          // 0..15
    const int s     = blockIdx.y;          // 0..7
    const int k0    = kb * 32;
    const int iBase = s * CI;

    // ---- zero-pad entries u in {0,8,9} ----
    for (int e = tid; e < CI * ROWS * 3; e += THREADS) {
        int i = e / (ROWS * 3);
        int r = e - i * (ROWS * 3);
        int row = r / 3;
        int z = r - row * 3;                    // 0,1,2 -> u = 0,8,9
        int u = (z == 0) ? 0 : (7 + z);
        sInd[(i * ROWS + row) * 10 + u] = make_float2(0.f, 0.f);
    }

    // ---- stage input slab, width roll baked in, duplicated pairs ----
    for (int e = tid; e < 2 * CI * 49; e += THREADS) {
        int o  = e / (CI * 49);
        int r  = e - o * (CI * 49);
        int i  = r / 49;
        int p  = r - i * 49;
        int n  = p / 7;
        int mw = p - n * 7;
        float v = x[(o * 512 + iBase + i) * 49 + p];
        int m = mw + 1; if (m == 7) m = 0;      // width roll +1
        sInd[(i * ROWS + (o * 7 + n)) * 10 + (m + 1)] = make_float2(v, v); // f[u]=r[u-1]
    }

    // ---- stage weight pairs: kp owns channels (k0+kp, k0+16+kp) ----
    for (int e = tid; e < CI * 16 * 3; e += THREADS) {
        int i  = e / 48;
        int q  = e - i * 48;
        int kp = q / 3;
        int j  = q - kp * 3;
        float wa = w[(iBase + i) * 1536 + (k0 + kp) * 3 + j];
        float wb = w[(iBase + i) * 1536 + (k0 + 16 + kp) * 3 + j];
        if (j == 2) {
            float2 p2 = make_float2(wa, wb);
            sWb[i * 16 + kp] = *reinterpret_cast<ull*>(&p2);
        } else {
            float* dst = reinterpret_cast<float*>(&sWa[i * 16 + kp]);
            dst[j * 2 + 0] = wa;
            dst[j * 2 + 1] = wb;
        }
    }

    __syncthreads();

    // ---- compute ----
    const int warp  = tid >> 5;        // 0..27
    const int lane  = tid & 31;
    const int row   = warp >> 1;       // 0..13 = o*7+n
    const int half  = warp & 1;
    const int isub  = lane >> 4;       // 0..1
    const int kp    = lane & 15;       // 0..15
    const int o     = row / 7;
    const int n     = row - o * 7;
    const int iw    = half * 32 + isub * 16;   // local i start, 16 per lane

    ull A[7];
#pragma unroll
    for (int m = 0; m < 7; m++) A[m] = 0ull;

#pragma unroll 4
    for (int ii = 0; ii < 16; ii++) {
        const int i = iw + ii;
        const ulonglong2* pr =
            reinterpret_cast<const ulonglong2*>(&sInd[(i * ROWS + row) * 10]);
        ulonglong2 L0 = pr[0];   // p0,p1  (broadcast-within-subgroup LDS.128)
        ulonglong2 L1 = pr[1];   // p2,p3
        ulonglong2 L2 = pr[2];   // p4,p5
        ulonglong2 L3 = pr[3];   // p6,p7
        ulonglong2 L4 = pr[4];   // p8,pad
        ulonglong2 W01 = sWa[i * 16 + kp];
        ull        W2  = sWb[i * 16 + kp];
        ull p0 = L0.x, p1 = L0.y, p2 = L1.x, p3 = L1.y;
        ull p4 = L2.x, p5 = L2.y, p6 = L3.x, p7 = L3.y, p8 = L4.x;

        // A[m] += p[m]*w0 + p[m+1]*w1 + p[m+2]*w2
        A[0] = ffma2(p0, W01.x, A[0]); A[0] = ffma2(p1, W01.y, A[0]); A[0] = ffma2(p2, W2, A[0]);
        A[1] = ffma2(p1, W01.x, A[1]); A[1] = ffma2(p2, W01.y, A[1]); A[1] = ffma2(p3, W2, A[1]);
        A[2] = ffma2(p2, W01.x, A[2]); A[2] = ffma2(p3, W01.y, A[2]); A[2] = ffma2(p4, W2, A[2]);
        A[3] = ffma2(p3, W01.x, A[3]); A[3] = ffma2(p4, W01.y, A[3]); A[3] = ffma2(p5, W2, A[3]);
        A[4] = ffma2(p4, W01.x, A[4]); A[4] = ffma2(p5, W01.y, A[4]); A[4] = ffma2(p6, W2, A[4]);
        A[5] = ffma2(p5, W01.x, A[5]); A[5] = ffma2(p6, W01.y, A[5]); A[5] = ffma2(p7, W2, A[5]);
        A[6] = ffma2(p6, W01.x, A[6]); A[6] = ffma2(p7, W01.y, A[6]); A[6] = ffma2(p8, W2, A[6]);
    }

    // ---- merge isub halves within the warp (shfl.xor 16) ----
#pragma unroll
    for (int m = 0; m < 7; m++) {
        ull other = __shfl_xor_sync(0xffffffffu, A[m], 16);
        A[m] = fadd2(A[m], other);
    }

    // ---- merge ihalf via smem (overlay on dead sInd) ----
    float2* red = reinterpret_cast<float2*>(dynsmem);   // 1568 float2 = 12.5 KB
    __syncthreads();
    if (half == 1 && isub == 0) {
#pragma unroll
        for (int m = 0; m < 7; m++)
            red[(row * 16 + kp) * 7 + m] = *reinterpret_cast<float2*>(&A[m]);
    }
    __syncthreads();

    // ---- REDG atomics straight into out (height roll baked in) ----
    if (half == 0 && isub == 0) {
        int nOut = n + 1; if (nOut == 7) nOut = 0;
        const int ca = (o * 512 + k0 + kp) * 49 + nOut * 7;
        const int cb = ca + 16 * 49;
#pragma unroll
        for (int m = 0; m < 7; m++) {
            float2 a = *reinterpret_cast<float2*>(&A[m]);
            float2 b = red[(row * 16 + kp) * 7 + m];
            atomicAdd(&out[ca + m], a.x + b.x);
            atomicAdd(&out[cb + m], a.y + b.y);
        }
    }
}

extern "C" void kernel_launch(void* const* d_in, const int* in_sizes, int n_in,
                              void* d_out, int out_size)
{
    const float* x = (const float*)d_in[0];
    const float* w = (const float*)d_in[1];
    float* out = (float*)d_out;

    cudaFuncSetAttribute(conv_atomic, cudaFuncAttributeMaxDynamicSharedMemorySize, SMEM_TOT);
    cudaMemsetAsync(out, 0, (size_t)out_size * sizeof(float));
    conv_atomic<<<dim3(NKT, S_SPLITS), THREADS, SMEM_TOT>>>(x, w, out);
}